// round 13
// baseline (speedup 1.0000x reference)
#include <cuda_runtime.h>
#include <cuda_bf16.h>
#include <cstdint>
#include <math.h>

#define B_      8
#define L_      2048
#define NN      (B_*L_)          // 16384 nodes
#define KNB     30
#define NE      (NN*KNB)         // 491520 edges
#define HID_    64
#define NH      4
#define DH      16
#define NRBF    16
#define FDIM    1038
#define NLAYERS 4
#define FFN     256

// ---------------- device scratch (static globals: no allocation allowed) ----
__device__ int   g_idx[NE];
__device__ float g_dnb[NE];
__device__ __align__(16) __nv_bfloat16 g_hEhi[(size_t)NE*HID_];  // edge feats hi
__device__ __align__(16) __nv_bfloat16 g_hElo[(size_t)NE*HID_];  // edge feats lo
__device__ float g_hV[(size_t)NN*HID_];
__device__ float g_Q [(size_t)NN*HID_];
__device__ float g_upd[(size_t)NN*HID_];
__device__ float g_hmid[(size_t)NN*HID_];
__device__ float g_ffn[(size_t)NN*FFN];
__device__ float g_P[(size_t)NN*128];          // per-node [K_n(64)+bK | V_n(64)+bV]
__device__ __align__(16) __nv_bfloat16 g_Bthi[128*64];  // [n][k] split weights (K=64)
__device__ __align__(16) __nv_bfloat16 g_Btlo[128*64];

// bf16 warp MMA m16n8k16 (row.col), fp32 accumulate — valid on plain sm_103
__device__ __forceinline__ void mma16816(float* d, const uint32_t* a, const uint32_t* b) {
    asm volatile(
      "mma.sync.aligned.m16n8k16.row.col.f32.bf16.bf16.f32 "
      "{%0,%1,%2,%3}, {%4,%5,%6,%7}, {%8,%9}, {%0,%1,%2,%3};"
      : "+f"(d[0]), "+f"(d[1]), "+f"(d[2]), "+f"(d[3])
      : "r"(a[0]), "r"(a[1]), "r"(a[2]), "r"(a[3]), "r"(b[0]), "r"(b[1]));
}

// ============================================================================
// 1. KNN: per node, 30 smallest D_adj with smaller-index tie-break
// ============================================================================
__global__ void knn_kernel(const float* __restrict__ coords,
                           const float* __restrict__ maskp)
{
    __shared__ float sx[L_], sy[L_], sz[L_], sm[L_];
    __shared__ float sd[L_];
    __shared__ float rv[8];
    __shared__ int   ri[8];
    __shared__ float s_dmax;

    int node = blockIdx.x;
    int b = node / L_;
    int i = node - b*L_;
    int tid = threadIdx.x;

    for (int j = tid; j < L_; j += 256) {
        size_t base = (size_t)(b*L_ + j)*3;
        sx[j] = coords[base+0];
        sy[j] = coords[base+1];
        sz[j] = coords[base+2];
        sm[j] = maskp[b*L_ + j];
    }
    __syncthreads();

    float cx = sx[i], cy = sy[i], cz = sz[i], mi = sm[i];

    float tmax = -1.f;
    for (int j = tid; j < L_; j += 256) {
        float dx = cx - sx[j], dy = cy - sy[j], dz = cz - sz[j];
        float d = sqrtf(dx*dx + dy*dy + dz*dz + 1e-6f);
        sd[j] = d;
        tmax = fmaxf(tmax, d);
    }
    #pragma unroll
    for (int off = 16; off; off >>= 1)
        tmax = fmaxf(tmax, __shfl_xor_sync(0xffffffffu, tmax, off));
    if ((tid & 31) == 0) rv[tid >> 5] = tmax;
    __syncthreads();
    if (tid == 0) {
        float m = rv[0];
        #pragma unroll
        for (int w = 1; w < 8; w++) m = fmaxf(m, rv[w]);
        s_dmax = m;
    }
    __syncthreads();
    float dmax = s_dmax;

    for (int j = tid; j < L_; j += 256)
        sd[j] = sd[j] + (1.f - mi*sm[j]) * dmax;
    __syncthreads();

    for (int k = 0; k < KNB; k++) {
        float best = 3.4e38f; int bi = 0x7fffffff;
        for (int j = tid; j < L_; j += 256) {
            float v = sd[j];
            if (v < best) { best = v; bi = j; }
        }
        #pragma unroll
        for (int off = 16; off; off >>= 1) {
            float ov = __shfl_xor_sync(0xffffffffu, best, off);
            int   oi = __shfl_xor_sync(0xffffffffu, bi,   off);
            if (ov < best || (ov == best && oi < bi)) { best = ov; bi = oi; }
        }
        if ((tid & 31) == 0) { rv[tid >> 5] = best; ri[tid >> 5] = bi; }
        __syncthreads();
        if (tid == 0) {
            float bv = rv[0]; int bj = ri[0];
            #pragma unroll
            for (int w = 1; w < 8; w++)
                if (rv[w] < bv || (rv[w] == bv && ri[w] < bj)) { bv = rv[w]; bj = ri[w]; }
            g_idx[node*KNB + k] = bj;
            g_dnb[node*KNB + k] = bv;
            sd[bj] = 3.0e38f;
        }
        __syncthreads();
    }
}

// ============================================================================
// 2. Edge features: rbf -> @W_ee -> LN -> @W_ep + b_ep => bf16 hi/lo split
// ============================================================================
__global__ void edge_kernel(const float* __restrict__ Wee,
                            const float* __restrict__ geln,
                            const float* __restrict__ beln,
                            const float* __restrict__ Wep,
                            const float* __restrict__ bep)
{
    __shared__ float sWee[256], sWep[1024], sg[16], sb[16], sbep[64];
    __shared__ float srbf[4][16], sy[4][16];

    int tid = threadIdx.x;
    sWee[tid] = Wee[tid];
    #pragma unroll
    for (int t = tid; t < 1024; t += 256) sWep[t] = Wep[t];
    if (tid < 16) { sg[tid] = geln[tid]; sb[tid] = beln[tid]; }
    if (tid < 64) sbep[tid] = bep[tid];
    __syncthreads();

    int ebase = blockIdx.x * 16;
    int sub = tid >> 6;
    int t   = tid & 63;

    for (int it = 0; it < 4; it++) {
        int e = ebase + it*4 + sub;
        float dval = g_dnb[e];
        if (t < 16) {
            float mu = 2.0f + (float)t * (20.0f/15.0f);
            float z = (dval - mu) * 0.8f;
            srbf[sub][t] = expf(-z*z);
        }
        __syncthreads();
        if (t < 16) {
            float acc = 0.f;
            #pragma unroll
            for (int s = 0; s < 16; s++) acc += srbf[sub][s] * sWee[s*16 + t];
            sy[sub][t] = acc;
        }
        __syncthreads();
        float mean = 0.f;
        #pragma unroll
        for (int s = 0; s < 16; s++) mean += sy[sub][s];
        mean *= (1.f/16.f);
        float var = 0.f;
        #pragma unroll
        for (int s = 0; s < 16; s++) { float d = sy[sub][s]-mean; var += d*d; }
        var *= (1.f/16.f);
        float inv = 1.f / sqrtf(var + 1e-5f);
        float acc = sbep[t];
        #pragma unroll
        for (int s = 0; s < 16; s++) {
            float zv = (sy[sub][s]-mean)*inv*sg[s] + sb[s];
            acc += zv * sWep[s*64 + t];
        }
        __nv_bfloat16 hi = __float2bfloat16_rn(acc);
        g_hEhi[(size_t)e*64 + t] = hi;
        g_hElo[(size_t)e*64 + t] = __float2bfloat16_rn(acc - __bfloat162float(hi));
        __syncthreads();
    }
}

// ============================================================================
// 3. Generic GEMM: C tile(128x64) = A[M,K] @ B[K,ldb](cols col0..col0+63) + bias
// ============================================================================
__global__ void gemm_bias_kernel(const float* __restrict__ A,
                                 const float* __restrict__ Bw,
                                 const float* __restrict__ bias,
                                 float* __restrict__ C,
                                 int K, int ldb, int ldc, int relu)
{
    __shared__ float As[16][128];
    __shared__ float Bs[16][64];
    int tid = threadIdx.x;
    int tx = tid & 15, ty = tid >> 4;
    int m0 = blockIdx.x * 128;
    int col0 = blockIdx.y * 64;

    float acc[8][4];
    #pragma unroll
    for (int i = 0; i < 8; i++)
        #pragma unroll
        for (int j = 0; j < 4; j++) acc[i][j] = 0.f;

    for (int k0 = 0; k0 < K; k0 += 16) {
        #pragma unroll
        for (int i = 0; i < 8; i++) {
            int idx = tid + i*256;
            int m = idx >> 4, kk = idx & 15;
            int kg = k0 + kk;
            As[kk][m] = (kg < K) ? A[(size_t)(m0+m)*K + kg] : 0.f;
        }
        #pragma unroll
        for (int i = 0; i < 4; i++) {
            int idx = tid + i*256;
            int kk = idx >> 6, n = idx & 63;
            int kg = k0 + kk;
            Bs[kk][n] = (kg < K) ? Bw[(size_t)kg*ldb + col0 + n] : 0.f;
        }
        __syncthreads();
        #pragma unroll
        for (int kk = 0; kk < 16; kk++) {
            float a[8], bb[4];
            #pragma unroll
            for (int i = 0; i < 8; i++) a[i] = As[kk][ty*8 + i];
            #pragma unroll
            for (int j = 0; j < 4; j++) bb[j] = Bs[kk][tx + j*16];
            #pragma unroll
            for (int i = 0; i < 8; i++)
                #pragma unroll
                for (int j = 0; j < 4; j++) acc[i][j] += a[i]*bb[j];
        }
        __syncthreads();
    }
    #pragma unroll
    for (int j = 0; j < 4; j++) {
        int n = tx + j*16;
        float bv = bias[col0 + n];
        #pragma unroll
        for (int i = 0; i < 8; i++) {
            float v = acc[i][j] + bv;
            if (relu) v = fmaxf(v, 0.f);
            C[(size_t)(m0 + ty*8 + i)*ldc + col0 + n] = v;
        }
    }
}

// ============================================================================
// 3b. Fused Q / K-node / V-node projections (blockIdx.y selects output)
//     y=0: g_Q = h_V@WQ+bQ ; y=1: g_P[:,0:64] = h_V@WKn+bK ; y=2: g_P[:,64:]
// ============================================================================
__global__ void qp_kernel(const float* __restrict__ hV,
                          const float* __restrict__ WQ, const float* __restrict__ bQ,
                          const float* __restrict__ WKn, const float* __restrict__ bKv,
                          const float* __restrict__ WVn, const float* __restrict__ bVv)
{
    __shared__ float As[16][128];
    __shared__ float Bs[16][64];
    int tid = threadIdx.x;
    int tx = tid & 15, ty = tid >> 4;
    int m0 = blockIdx.x * 128;

    const float* Bw; const float* bias; float* C; int ldc;
    if (blockIdx.y == 0)      { Bw = WQ;  bias = bQ;  C = g_Q;     ldc = 64;  }
    else if (blockIdx.y == 1) { Bw = WKn; bias = bKv; C = g_P;     ldc = 128; }
    else                      { Bw = WVn; bias = bVv; C = g_P + 64; ldc = 128; }

    float acc[8][4];
    #pragma unroll
    for (int i = 0; i < 8; i++)
        #pragma unroll
        for (int j = 0; j < 4; j++) acc[i][j] = 0.f;

    for (int k0 = 0; k0 < 64; k0 += 16) {
        #pragma unroll
        for (int i = 0; i < 8; i++) {
            int idx = tid + i*256;
            int m = idx >> 4, kk = idx & 15;
            As[kk][m] = hV[(size_t)(m0+m)*64 + k0 + kk];
        }
        #pragma unroll
        for (int i = 0; i < 4; i++) {
            int idx = tid + i*256;
            int kk = idx >> 6, n = idx & 63;
            Bs[kk][n] = Bw[(size_t)(k0+kk)*64 + n];
        }
        __syncthreads();
        #pragma unroll
        for (int kk = 0; kk < 16; kk++) {
            float a[8], bb[4];
            #pragma unroll
            for (int i = 0; i < 8; i++) a[i] = As[kk][ty*8 + i];
            #pragma unroll
            for (int j = 0; j < 4; j++) bb[j] = Bs[kk][tx + j*16];
            #pragma unroll
            for (int i = 0; i < 8; i++)
                #pragma unroll
                for (int j = 0; j < 4; j++) acc[i][j] += a[i]*bb[j];
        }
        __syncthreads();
    }
    #pragma unroll
    for (int j = 0; j < 4; j++) {
        int n = tx + j*16;
        float bv = bias[n];
        #pragma unroll
        for (int i = 0; i < 8; i++)
            C[(size_t)(m0 + ty*8 + i)*ldc + n] = acc[i][j] + bv;
    }
}

// ============================================================================
// 4a. KV weight prep: Bt[n][k] = edge-half of [WK|WV] (rows 0..63), bf16 hi/lo
// ============================================================================
__global__ void kv_prep_kernel(const float* __restrict__ WK,
                               const float* __restrict__ WV)
{
    int idx = blockIdx.x * 256 + threadIdx.x;   // 8192 total
    int n = idx >> 6, k = idx & 63;
    float w = (n < 64) ? WK[k*64 + n] : WV[k*64 + (n - 64)];
    __nv_bfloat16 hi = __float2bfloat16_rn(w);
    g_Bthi[idx] = hi;
    g_Btlo[idx] = __float2bfloat16_rn(w - __bfloat162float(hi));
}

// ============================================================================
// 4b. FUSED edge-GEMM + attention.
//     Block = 4 nodes x 32 padded edge slots (slots 30,31 zero) = 128 MMA rows.
//     R = hE @ Bt^T (bf16 3-term, fp32 acc) -> smem KV[128][133]
//     KV += P[nbr]  (node term, L2-resident gather)
//     softmax attention per (node, head) -> g_upd.   No g_R round-trip.
// ============================================================================
#define EST    72
#define KVST   133
#define F_SMEM (4*128*EST*2)     // 73728 B; KV region (128*133*4=68096) overlaps

__global__ void __launch_bounds__(256, 2)
fused_kv_attn_kernel(const float* __restrict__ maskp)
{
    extern __shared__ __align__(16) char smem[];
    __nv_bfloat16* AHI = (__nv_bfloat16*)smem;
    __nv_bfloat16* ALO = AHI + 128*EST;
    __nv_bfloat16* BHI = ALO + 128*EST;
    __nv_bfloat16* BLO = BHI + 128*EST;
    float* KVsm = (float*)smem;              // reused after MMA

    __shared__ float qsm[4][64];
    __shared__ float sma[4][32];
    __shared__ int   snbr[4][32];

    int tid = threadIdx.x;
    int n0 = blockIdx.x * 4;

    // ---- stage Q, neighbor ids, attend-mask ----
    {
        int g = tid >> 6, c = tid & 63;
        qsm[g][c] = g_Q[(size_t)(n0 + g)*64 + c];
    }
    if (tid < 128) {
        int g = tid >> 5, s = tid & 31;
        int node = n0 + g;
        if (s < KNB) {
            int b = node / L_;
            int nbr = b*L_ + g_idx[node*KNB + s];
            snbr[g][s] = nbr;
            sma[g][s] = maskp[nbr] * maskp[node];
        } else {
            snbr[g][s] = 0;
            sma[g][s] = 0.f;
        }
    }

    // ---- load A (edge features, padded) and B (weights) tiles ----
    {
        int r = tid >> 1, half = tid & 1;
        int g = r >> 5, s = r & 31;
        uint4* dah = (uint4*)(AHI + r*EST + half*32);
        uint4* dal = (uint4*)(ALO + r*EST + half*32);
        if (s < KNB) {
            int e = (n0 + g)*KNB + s;
            const uint4* sah = (const uint4*)(g_hEhi + (size_t)e*64) + half*4;
            const uint4* sal = (const uint4*)(g_hElo + (size_t)e*64) + half*4;
            #pragma unroll
            for (int j = 0; j < 4; j++) { dah[j] = sah[j]; dal[j] = sal[j]; }
        } else {
            uint4 z = make_uint4(0,0,0,0);
            #pragma unroll
            for (int j = 0; j < 4; j++) { dah[j] = z; dal[j] = z; }
        }
        const uint4* sbh = (const uint4*)(g_Bthi + r*64) + half*4;
        const uint4* sbl = (const uint4*)(g_Btlo + r*64) + half*4;
        uint4* dbh = (uint4*)(BHI + r*EST + half*32);
        uint4* dbl = (uint4*)(BLO + r*EST + half*32);
        #pragma unroll
        for (int j = 0; j < 4; j++) { dbh[j] = sbh[j]; dbl[j] = sbl[j]; }
    }
    __syncthreads();

    int lane = tid & 31, warp = tid >> 5;
    int wm = warp & 3, wn = warp >> 2;        // 4 x 2 warp grid
    int gid = lane >> 2, tq = lane & 3;

    float acc[2][8][4];
    #pragma unroll
    for (int mt = 0; mt < 2; mt++)
        #pragma unroll
        for (int nt = 0; nt < 8; nt++)
            #pragma unroll
            for (int q = 0; q < 4; q++) acc[mt][nt][q] = 0.f;

    const __nv_bfloat16* Asel[3] = {AHI, AHI, ALO};
    const __nv_bfloat16* Bsel[3] = {BHI, BLO, BHI};

    #pragma unroll
    for (int t = 0; t < 3; t++) {
        const __nv_bfloat16* As = Asel[t];
        const __nv_bfloat16* Bs = Bsel[t];
        #pragma unroll
        for (int ks = 0; ks < 4; ks++) {
            int k0 = ks*16;
            uint32_t a[2][4], b[8][2];
            #pragma unroll
            for (int mt = 0; mt < 2; mt++) {
                const __nv_bfloat16* p = As + (wm*32 + mt*16 + gid)*EST + k0 + tq*2;
                a[mt][0] = *(const uint32_t*)(p);
                a[mt][1] = *(const uint32_t*)(p + 8*EST);
                a[mt][2] = *(const uint32_t*)(p + 8);
                a[mt][3] = *(const uint32_t*)(p + 8*EST + 8);
            }
            #pragma unroll
            for (int nt = 0; nt < 8; nt++) {
                const __nv_bfloat16* p = Bs + (wn*64 + nt*8 + gid)*EST + k0 + tq*2;
                b[nt][0] = *(const uint32_t*)(p);
                b[nt][1] = *(const uint32_t*)(p + 8);
            }
            #pragma unroll
            for (int mt = 0; mt < 2; mt++)
                #pragma unroll
                for (int nt = 0; nt < 8; nt++)
                    mma16816(acc[mt][nt], a[mt], b[nt]);
        }
    }
    __syncthreads();    // all smem reads done; A/B region becomes KV

    // ---- store accumulators: KVsm[row][col] = R  (row = edge slot) ----
    #pragma unroll
    for (int mt = 0; mt < 2; mt++) {
        int r0 = wm*32 + mt*16 + gid;
        #pragma unroll
        for (int nt = 0; nt < 8; nt++) {
            int col = wn*64 + nt*8 + tq*2;
            KVsm[r0*KVST + col]     = acc[mt][nt][0];
            KVsm[r0*KVST + col + 1] = acc[mt][nt][1];
            KVsm[(r0+8)*KVST + col]     = acc[mt][nt][2];
            KVsm[(r0+8)*KVST + col + 1] = acc[mt][nt][3];
        }
    }
    __syncthreads();

    // ---- add node term P[nbr] (includes bK|bV); L2-resident gather ----
    {
        int r = tid >> 1, half = tid & 1;
        int g = r >> 5, s = r & 31;
        if (s < KNB) {
            int nbr = snbr[g][s];
            const float4* ps = (const float4*)(g_P + (size_t)nbr*128 + half*64);
            float* row = KVsm + r*KVST + half*64;
            #pragma unroll
            for (int j = 0; j < 16; j++) {
                float4 v = ps[j];
                row[j*4+0] += v.x; row[j*4+1] += v.y;
                row[j*4+2] += v.z; row[j*4+3] += v.w;
            }
        }
    }
    __syncthreads();

    // ---- attention: 8 warps x 2 (node,head) pairs ----
    const float NEGMIN = -3.402823466e38f;
    #pragma unroll
    for (int p = 0; p < 2; p++) {
        int idx = warp*2 + p;
        int g = idx >> 2, h = idx & 3;
        int node = n0 + g;

        float ma = sma[g][lane & 31];
        float lg = NEGMIN;
        if (lane < KNB) {
            const float* krow = KVsm + (g*32 + lane)*KVST + h*16;
            float s = 0.f;
            #pragma unroll
            for (int d = 0; d < 16; d++) s += qsm[g][h*16 + d] * krow[d];
            s *= 0.25f;
            lg = (ma > 0.f) ? s : NEGMIN;
        }
        float mx = lg;
        #pragma unroll
        for (int off = 16; off; off >>= 1)
            mx = fmaxf(mx, __shfl_xor_sync(0xffffffffu, mx, off));
        float pe = (lane < KNB) ? expf(lg - mx) : 0.f;
        float sum = pe;
        #pragma unroll
        for (int off = 16; off; off >>= 1)
            sum += __shfl_xor_sync(0xffffffffu, sum, off);
        float att = (lane < KNB) ? (pe / sum) * ma : 0.f;

        float u = 0.f;
        #pragma unroll
        for (int s = 0; s < KNB; s++) {
            float a = __shfl_sync(0xffffffffu, att, s);
            u += a * KVsm[(g*32 + s)*KVST + 64 + h*16 + (lane & 15)];
        }
        if (lane < 16)
            g_upd[(size_t)node*64 + h*16 + lane] = u;
    }
}

// ============================================================================
// 6. GEMM (K x 64) + bias + residual + LayerNorm (+ optional mask) epilogue
// ============================================================================
__global__ void gemm_ln_kernel(const float* __restrict__ A,
                               const float* __restrict__ Bw,
                               const float* __restrict__ bias,
                               const float* __restrict__ resid,
                               const float* __restrict__ gamma,
                               const float* __restrict__ beta,
                               const float* __restrict__ maskp,
                               float* __restrict__ Out,
                               int K)
{
    __shared__ float As[16][128];
    __shared__ float Bs[16][64];
    __shared__ float Cs[128][65];
    int tid = threadIdx.x;
    int tx = tid & 15, ty = tid >> 4;
    int m0 = blockIdx.x * 128;

    float acc[8][4];
    #pragma unroll
    for (int i = 0; i < 8; i++)
        #pragma unroll
        for (int j = 0; j < 4; j++) acc[i][j] = 0.f;

    for (int k0 = 0; k0 < K; k0 += 16) {
        #pragma unroll
        for (int i = 0; i < 8; i++) {
            int idx = tid + i*256;
            int m = idx >> 4, kk = idx & 15;
            As[kk][m] = A[(size_t)(m0+m)*K + k0 + kk];
        }
        #pragma unroll
        for (int i = 0; i < 4; i++) {
            int idx = tid + i*256;
            int kk = idx >> 6, n = idx & 63;
            Bs[kk][n] = Bw[(size_t)(k0+kk)*64 + n];
        }
        __syncthreads();
        #pragma unroll
        for (int kk = 0; kk < 16; kk++) {
            float a[8], bb[4];
            #pragma unroll
            for (int i = 0; i < 8; i++) a[i] = As[kk][ty*8 + i];
            #pragma unroll
            for (int j = 0; j < 4; j++) bb[j] = Bs[kk][tx + j*16];
            #pragma unroll
            for (int i = 0; i < 8; i++)
                #pragma unroll
                for (int j = 0; j < 4; j++) acc[i][j] += a[i]*bb[j];
        }
        __syncthreads();
    }
    #pragma unroll
    for (int j = 0; j < 4; j++) {
        int n = tx + j*16;
        float bv = bias[n];
        #pragma unroll
        for (int i = 0; i < 8; i++) {
            int row = ty*8 + i;
            Cs[row][n] = acc[i][j] + bv + resid[(size_t)(m0+row)*64 + n];
        }
    }
    __syncthreads();

    int wid = tid >> 5, lane = tid & 31;
    for (int r = 0; r < 16; r++) {
        int row = wid*16 + r;
        float x0 = Cs[row][lane], x1 = Cs[row][lane+32];
        float s = x0 + x1;
        #pragma unroll
        for (int off = 16; off; off >>= 1)
            s += __shfl_xor_sync(0xffffffffu, s, off);
        float mean = s * (1.f/64.f);
        float d0 = x0 - mean, d1 = x1 - mean;
        float vs = d0*d0 + d1*d1;
        #pragma unroll
        for (int off = 16; off; off >>= 1)
            vs += __shfl_xor_sync(0xffffffffu, vs, off);
        float inv = 1.f / sqrtf(vs*(1.f/64.f) + 1e-5f);
        float mk = maskp ? maskp[m0 + row] : 1.f;
        size_t ob = (size_t)(m0+row)*64;
        Out[ob + lane]      = (d0*inv*gamma[lane]    + beta[lane])    * mk;
        Out[ob + lane + 32] = (d1*inv*gamma[lane+32] + beta[lane+32]) * mk;
    }
}

// ============================================================================
// 7. Output head
// ============================================================================
__global__ void out_kernel(const float* __restrict__ Wout,
                           const float* __restrict__ bout,
                           float* __restrict__ out)
{
    int tid = threadIdx.x;
    int ws = tid >> 5, lane = tid & 31;
    int n = blockIdx.x * 8 + ws;
    float v = g_hV[(size_t)n*64 + lane] * Wout[lane]
            + g_hV[(size_t)n*64 + 32 + lane] * Wout[32 + lane];
    #pragma unroll
    for (int off = 16; off; off >>= 1)
        v += __shfl_xor_sync(0xffffffffu, v, off);
    if (lane == 0) out[n] = v + bout[0];
}

// ============================================================================
extern "C" void kernel_launch(void* const* d_in, const int* in_sizes, int n_in,
                              void* d_out, int out_size)
{
    const float* coords = (const float*)d_in[0];
    const float* nodef  = (const float*)d_in[1];
    const float* maskp  = (const float*)d_in[2];
    const float* W_node = (const float*)d_in[3];
    const float* b_node = (const float*)d_in[4];
    const float* W_ee   = (const float*)d_in[5];
    const float* g_eln  = (const float*)d_in[6];
    const float* b_eln  = (const float*)d_in[7];
    const float* W_ep   = (const float*)d_in[8];
    const float* b_ep   = (const float*)d_in[9];
    const float* WQ = (const float*)d_in[10];
    const float* bQ = (const float*)d_in[11];
    const float* WK = (const float*)d_in[12];
    const float* bK = (const float*)d_in[13];
    const float* WV = (const float*)d_in[14];
    const float* bV = (const float*)d_in[15];
    const float* WO = (const float*)d_in[16];
    const float* bO = (const float*)d_in[17];
    const float* g1 = (const float*)d_in[18];
    const float* b1 = (const float*)d_in[19];
    const float* W1 = (const float*)d_in[20];
    const float* bf1= (const float*)d_in[21];
    const float* W2 = (const float*)d_in[22];
    const float* bf2= (const float*)d_in[23];
    const float* g2 = (const float*)d_in[24];
    const float* b2 = (const float*)d_in[25];
    const float* W_out = (const float*)d_in[26];
    const float* b_out = (const float*)d_in[27];
    float* outp = (float*)d_out;

    void *pv;
    cudaGetSymbolAddress(&pv, g_hV);   float* p_hV   = (float*)pv;
    cudaGetSymbolAddress(&pv, g_upd);  float* p_upd  = (float*)pv;
    cudaGetSymbolAddress(&pv, g_hmid); float* p_hmid = (float*)pv;
    cudaGetSymbolAddress(&pv, g_ffn);  float* p_ffn  = (float*)pv;

    cudaFuncSetAttribute(fused_kv_attn_kernel,
                         cudaFuncAttributeMaxDynamicSharedMemorySize, F_SMEM);

    knn_kernel<<<NN, 256>>>(coords, maskp);
    edge_kernel<<<NE/16, 256>>>(W_ee, g_eln, b_eln, W_ep, b_ep);

    gemm_bias_kernel<<<dim3(NN/128, 1), 256>>>(nodef, W_node, b_node, p_hV,
                                               FDIM, HID_, HID_, 0);

    for (int l = 0; l < NLAYERS; l++) {
        const float* WQl = WQ + (size_t)l*HID_*HID_;
        const float* WKl = WK + (size_t)l*2*HID_*HID_;
        const float* WVl = WV + (size_t)l*2*HID_*HID_;
        const float* WOl = WO + (size_t)l*HID_*HID_;
        const float* W1l = W1 + (size_t)l*HID_*FFN;
        const float* W2l = W2 + (size_t)l*FFN*HID_;

        // Q | K-node | V-node in one launch (node halves of WK/WV are rows 64..127)
        qp_kernel<<<dim3(NN/128, 3), 256>>>(p_hV, WQl, bQ + l*HID_,
                                            WKl + 64*64, bK + l*HID_,
                                            WVl + 64*64, bV + l*HID_);
        // edge-half weights -> bf16 hi/lo
        kv_prep_kernel<<<32, 256>>>(WKl, WVl);
        // fused edge-GEMM + attention -> g_upd
        fused_kv_attn_kernel<<<NN/4, 256, F_SMEM>>>(maskp);
        // h_mid = LN(h_V + upd@WO + bO)
        gemm_ln_kernel<<<NN/128, 256>>>(p_upd, WOl, bO + l*HID_, p_hV,
                                        g1 + l*HID_, b1 + l*HID_, nullptr,
                                        p_hmid, HID_);
        // ffn = relu(h_mid @ W1 + bf1)
        gemm_bias_kernel<<<dim3(NN/128, 4), 256>>>(p_hmid, W1l, bf1 + l*FFN, p_ffn,
                                                   HID_, FFN, FFN, 1);
        // h_V = LN(h_mid + ffn@W2 + bf2) * mask
        gemm_ln_kernel<<<NN/128, 256>>>(p_ffn, W2l, bf2 + l*HID_, p_hmid,
                                        g2 + l*HID_, b2 + l*HID_, maskp,
                                        p_hV, FFN);
    }

    out_kernel<<<NN/8, 256>>>(W_out, b_out, outp);
}

// round 16
// speedup vs baseline: 1.1272x; 1.1272x over previous
#include <cuda_runtime.h>
#include <cuda_bf16.h>
#include <cstdint>
#include <math.h>

#define B_      8
#define L_      2048
#define NN      (B_*L_)          // 16384 nodes
#define KNB     30
#define NE      (NN*KNB)         // 491520 edges
#define HID_    64
#define NH      4
#define DH      16
#define NRBF    16
#define FDIM    1038
#define NLAYERS 4
#define FFN     256

// ---------------- device scratch (static globals: no allocation allowed) ----
__device__ int   g_idx[NE];
__device__ float g_dnb[NE];
__device__ __align__(16) __nv_bfloat16 g_hEhi[(size_t)NE*HID_];  // edge feats hi
__device__ __align__(16) __nv_bfloat16 g_hElo[(size_t)NE*HID_];  // edge feats lo
__device__ float g_hV[(size_t)NN*HID_];
__device__ float g_Q [(size_t)NN*HID_];
__device__ float g_upd[(size_t)NN*HID_];
__device__ float g_hmid[(size_t)NN*HID_];
__device__ float g_ffn[(size_t)NN*FFN];
__device__ float g_R[(size_t)NE*128];          // per-edge [K_e(64) | V_e(64)] edge term
__device__ float g_P[(size_t)NN*128];          // per-node [K_n(64)+bK | V_n(64)+bV]
__device__ __align__(16) __nv_bfloat16 g_Bthi[128*64];  // [n][k] split weights (K=64)
__device__ __align__(16) __nv_bfloat16 g_Btlo[128*64];

// bf16 warp MMA m16n8k16 (row.col), fp32 accumulate — valid on plain sm_103
__device__ __forceinline__ void mma16816(float* d, const uint32_t* a, const uint32_t* b) {
    asm volatile(
      "mma.sync.aligned.m16n8k16.row.col.f32.bf16.bf16.f32 "
      "{%0,%1,%2,%3}, {%4,%5,%6,%7}, {%8,%9}, {%0,%1,%2,%3};"
      : "+f"(d[0]), "+f"(d[1]), "+f"(d[2]), "+f"(d[3])
      : "r"(a[0]), "r"(a[1]), "r"(a[2]), "r"(a[3]), "r"(b[0]), "r"(b[1]));
}

// ============================================================================
// 1. KNN (warp-per-node, REDUX selection): 30 smallest D_adj, index tie-break.
//    Grid 128 (= 8 batches x 16 groups), one wave. Block = 256 thr = 8 warps;
//    each warp handles 16 nodes sequentially. Distances live in a per-thread
//    smem column sd[t*256+tid] (64 per thread, conflict-free across lanes).
//    Selection round: u32-min REDUX on float bits (exact for positives), then
//    u32-min REDUX on candidate index for the exact smaller-index tie-break.
//    Only the winning lane invalidates + rescans its 64 values.
// ============================================================================
__global__ void __launch_bounds__(256, 1)
knn_kernel(const float* __restrict__ coords,
           const float* __restrict__ maskp)
{
    __shared__ float sx[L_], sy[L_], sz[L_], sm[L_];
    extern __shared__ float sd[];     // 64 * 256 floats = 64 KB

    int blk = blockIdx.x;
    int b  = blk >> 4;                // batch
    int g0 = (blk & 15) * 128;        // node group start within batch
    int tid = threadIdx.x;
    int warp = tid >> 5, lane = tid & 31;

    for (int j = tid; j < L_; j += 256) {
        size_t base = (size_t)(b*L_ + j)*3;
        sx[j] = coords[base+0];
        sy[j] = coords[base+1];
        sz[j] = coords[base+2];
        sm[j] = maskp[b*L_ + j];
    }
    __syncthreads();

    for (int nl = 0; nl < 16; nl++) {
        int i = g0 + warp*16 + nl;    // node within batch
        int node = b*L_ + i;
        float cx = sx[i], cy = sy[i], cz = sz[i], mi = sm[i];

        // distances + row max
        float dmax = -1.f;
        #pragma unroll
        for (int t = 0; t < 64; t++) {
            int j = t*32 + lane;
            float dx = cx - sx[j], dy = cy - sy[j], dz = cz - sz[j];
            float d = sqrtf(dx*dx + dy*dy + dz*dz + 1e-6f);
            sd[t*256 + tid] = d;
            dmax = fmaxf(dmax, d);
        }
        dmax = __uint_as_float(__reduce_max_sync(0xffffffffu, __float_as_uint(dmax)));

        // D_adj = D + (1 - mi*mj) * dmax ; lane-local argmin (ascending j keeps
        // the smallest index on value ties within a lane)
        float lmin = 3.4e38f; int lidx = 0x7fffffff;
        #pragma unroll
        for (int t = 0; t < 64; t++) {
            int j = t*32 + lane;
            float v = sd[t*256 + tid] + (1.f - mi*sm[j]) * dmax;
            sd[t*256 + tid] = v;
            if (v < lmin) { lmin = v; lidx = j; }
        }

        // 30 extraction rounds, no barriers
        #pragma unroll 1
        for (int k = 0; k < KNB; k++) {
            uint32_t mbits = __reduce_min_sync(0xffffffffu, __float_as_uint(lmin));
            uint32_t cand = (__float_as_uint(lmin) == mbits)
                          ? (uint32_t)lidx : 0x7fffffffu;
            int bi = (int)__reduce_min_sync(0xffffffffu, cand);
            if (lane == 0) {
                g_idx[node*KNB + k] = bi;
                g_dnb[node*KNB + k] = __uint_as_float(mbits);
            }
            if (lidx == bi) {               // unique owner lane (bi % 32 == lane)
                sd[(bi >> 5)*256 + tid] = 3.4e38f;
                lmin = 3.4e38f; lidx = 0x7fffffff;
                #pragma unroll
                for (int t = 0; t < 64; t++) {
                    float v = sd[t*256 + tid];
                    if (v < lmin) { lmin = v; lidx = t*32 + lane; }
                }
            }
        }
    }
}

// ============================================================================
// 2. Edge features: rbf -> @W_ee -> LN -> @W_ep + b_ep => bf16 hi/lo split
// ============================================================================
__global__ void edge_kernel(const float* __restrict__ Wee,
                            const float* __restrict__ geln,
                            const float* __restrict__ beln,
                            const float* __restrict__ Wep,
                            const float* __restrict__ bep)
{
    __shared__ float sWee[256], sWep[1024], sg[16], sb[16], sbep[64];
    __shared__ float srbf[4][16], sy[4][16];

    int tid = threadIdx.x;
    sWee[tid] = Wee[tid];
    #pragma unroll
    for (int t = tid; t < 1024; t += 256) sWep[t] = Wep[t];
    if (tid < 16) { sg[tid] = geln[tid]; sb[tid] = beln[tid]; }
    if (tid < 64) sbep[tid] = bep[tid];
    __syncthreads();

    int ebase = blockIdx.x * 16;
    int sub = tid >> 6;
    int t   = tid & 63;

    for (int it = 0; it < 4; it++) {
        int e = ebase + it*4 + sub;
        float dval = g_dnb[e];
        if (t < 16) {
            float mu = 2.0f + (float)t * (20.0f/15.0f);
            float z = (dval - mu) * 0.8f;
            srbf[sub][t] = expf(-z*z);
        }
        __syncthreads();
        if (t < 16) {
            float acc = 0.f;
            #pragma unroll
            for (int s = 0; s < 16; s++) acc += srbf[sub][s] * sWee[s*16 + t];
            sy[sub][t] = acc;
        }
        __syncthreads();
        float mean = 0.f;
        #pragma unroll
        for (int s = 0; s < 16; s++) mean += sy[sub][s];
        mean *= (1.f/16.f);
        float var = 0.f;
        #pragma unroll
        for (int s = 0; s < 16; s++) { float d = sy[sub][s]-mean; var += d*d; }
        var *= (1.f/16.f);
        float inv = 1.f / sqrtf(var + 1e-5f);
        float acc = sbep[t];
        #pragma unroll
        for (int s = 0; s < 16; s++) {
            float zv = (sy[sub][s]-mean)*inv*sg[s] + sb[s];
            acc += zv * sWep[s*64 + t];
        }
        __nv_bfloat16 hi = __float2bfloat16_rn(acc);
        g_hEhi[(size_t)e*64 + t] = hi;
        g_hElo[(size_t)e*64 + t] = __float2bfloat16_rn(acc - __bfloat162float(hi));
        __syncthreads();
    }
}

// ============================================================================
// 3. Generic GEMM: C tile(128x64) = A[M,K] @ B[K,ldb](cols col0..col0+63) + bias
// ============================================================================
__global__ void gemm_bias_kernel(const float* __restrict__ A,
                                 const float* __restrict__ Bw,
                                 const float* __restrict__ bias,
                                 float* __restrict__ C,
                                 int K, int ldb, int ldc, int relu)
{
    __shared__ float As[16][128];
    __shared__ float Bs[16][64];
    int tid = threadIdx.x;
    int tx = tid & 15, ty = tid >> 4;
    int m0 = blockIdx.x * 128;
    int col0 = blockIdx.y * 64;

    float acc[8][4];
    #pragma unroll
    for (int i = 0; i < 8; i++)
        #pragma unroll
        for (int j = 0; j < 4; j++) acc[i][j] = 0.f;

    for (int k0 = 0; k0 < K; k0 += 16) {
        #pragma unroll
        for (int i = 0; i < 8; i++) {
            int idx = tid + i*256;
            int m = idx >> 4, kk = idx & 15;
            int kg = k0 + kk;
            As[kk][m] = (kg < K) ? A[(size_t)(m0+m)*K + kg] : 0.f;
        }
        #pragma unroll
        for (int i = 0; i < 4; i++) {
            int idx = tid + i*256;
            int kk = idx >> 6, n = idx & 63;
            int kg = k0 + kk;
            Bs[kk][n] = (kg < K) ? Bw[(size_t)kg*ldb + col0 + n] : 0.f;
        }
        __syncthreads();
        #pragma unroll
        for (int kk = 0; kk < 16; kk++) {
            float a[8], bb[4];
            #pragma unroll
            for (int i = 0; i < 8; i++) a[i] = As[kk][ty*8 + i];
            #pragma unroll
            for (int j = 0; j < 4; j++) bb[j] = Bs[kk][tx + j*16];
            #pragma unroll
            for (int i = 0; i < 8; i++)
                #pragma unroll
                for (int j = 0; j < 4; j++) acc[i][j] += a[i]*bb[j];
        }
        __syncthreads();
    }
    #pragma unroll
    for (int j = 0; j < 4; j++) {
        int n = tx + j*16;
        float bv = bias[col0 + n];
        #pragma unroll
        for (int i = 0; i < 8; i++) {
            float v = acc[i][j] + bv;
            if (relu) v = fmaxf(v, 0.f);
            C[(size_t)(m0 + ty*8 + i)*ldc + col0 + n] = v;
        }
    }
}

// ============================================================================
// 3b. Fused Q / K-node / V-node projections (blockIdx.y selects output)
// ============================================================================
__global__ void qp_kernel(const float* __restrict__ hV,
                          const float* __restrict__ WQ, const float* __restrict__ bQ,
                          const float* __restrict__ WKn, const float* __restrict__ bKv,
                          const float* __restrict__ WVn, const float* __restrict__ bVv)
{
    __shared__ float As[16][128];
    __shared__ float Bs[16][64];
    int tid = threadIdx.x;
    int tx = tid & 15, ty = tid >> 4;
    int m0 = blockIdx.x * 128;

    const float* Bw; const float* bias; float* C; int ldc;
    if (blockIdx.y == 0)      { Bw = WQ;  bias = bQ;  C = g_Q;      ldc = 64;  }
    else if (blockIdx.y == 1) { Bw = WKn; bias = bKv; C = g_P;      ldc = 128; }
    else                      { Bw = WVn; bias = bVv; C = g_P + 64; ldc = 128; }

    float acc[8][4];
    #pragma unroll
    for (int i = 0; i < 8; i++)
        #pragma unroll
        for (int j = 0; j < 4; j++) acc[i][j] = 0.f;

    for (int k0 = 0; k0 < 64; k0 += 16) {
        #pragma unroll
        for (int i = 0; i < 8; i++) {
            int idx = tid + i*256;
            int m = idx >> 4, kk = idx & 15;
            As[kk][m] = hV[(size_t)(m0+m)*64 + k0 + kk];
        }
        #pragma unroll
        for (int i = 0; i < 4; i++) {
            int idx = tid + i*256;
            int kk = idx >> 6, n = idx & 63;
            Bs[kk][n] = Bw[(size_t)(k0+kk)*64 + n];
        }
        __syncthreads();
        #pragma unroll
        for (int kk = 0; kk < 16; kk++) {
            float a[8], bb[4];
            #pragma unroll
            for (int i = 0; i < 8; i++) a[i] = As[kk][ty*8 + i];
            #pragma unroll
            for (int j = 0; j < 4; j++) bb[j] = Bs[kk][tx + j*16];
            #pragma unroll
            for (int i = 0; i < 8; i++)
                #pragma unroll
                for (int j = 0; j < 4; j++) acc[i][j] += a[i]*bb[j];
        }
        __syncthreads();
    }
    #pragma unroll
    for (int j = 0; j < 4; j++) {
        int n = tx + j*16;
        float bv = bias[n];
        #pragma unroll
        for (int i = 0; i < 8; i++)
            C[(size_t)(m0 + ty*8 + i)*ldc + n] = acc[i][j] + bv;
    }
}

// ============================================================================
// 4a. KV weight prep: Bt[n][k] = edge-half of [WK|WV] (rows 0..63), bf16 hi/lo
// ============================================================================
__global__ void kv_prep_kernel(const float* __restrict__ WK,
                               const float* __restrict__ WV)
{
    int idx = blockIdx.x * 256 + threadIdx.x;   // 8192 total
    int n = idx >> 6, k = idx & 63;
    float w = (n < 64) ? WK[k*64 + n] : WV[k*64 + (n - 64)];
    __nv_bfloat16 hi = __float2bfloat16_rn(w);
    g_Bthi[idx] = hi;
    g_Btlo[idx] = __float2bfloat16_rn(w - __bfloat162float(hi));
}

// ============================================================================
// 4b. Edge-term GEMM on warp MMA: R[128e x 128n] = hE[128 x 64] @ Bt^T
//     bf16 3-term (hi*hi + hi*lo + lo*hi), fp32 accum.
// ============================================================================
#define EST 72
#define KV_SMEM (4*128*EST*2)

__global__ void __launch_bounds__(256, 2)
kv_mma_kernel()
{
    extern __shared__ __align__(16) char smem[];
    __nv_bfloat16* AHI = (__nv_bfloat16*)smem;
    __nv_bfloat16* ALO = AHI + 128*EST;
    __nv_bfloat16* BHI = ALO + 128*EST;
    __nv_bfloat16* BLO = BHI + 128*EST;

    int tid = threadIdx.x;
    int e0 = blockIdx.x * 128;

    {
        int r = tid >> 1, half = tid & 1;
        const uint4* sah = (const uint4*)(g_hEhi + (size_t)(e0 + r)*64) + half*4;
        const uint4* sal = (const uint4*)(g_hElo + (size_t)(e0 + r)*64) + half*4;
        const uint4* sbh = (const uint4*)(g_Bthi + r*64) + half*4;
        const uint4* sbl = (const uint4*)(g_Btlo + r*64) + half*4;
        uint4* dah = (uint4*)(AHI + r*EST + half*32);
        uint4* dal = (uint4*)(ALO + r*EST + half*32);
        uint4* dbh = (uint4*)(BHI + r*EST + half*32);
        uint4* dbl = (uint4*)(BLO + r*EST + half*32);
        #pragma unroll
        for (int j = 0; j < 4; j++) {
            dah[j] = sah[j];
            dal[j] = sal[j];
            dbh[j] = sbh[j];
            dbl[j] = sbl[j];
        }
    }
    __syncthreads();

    int lane = tid & 31, warp = tid >> 5;
    int wm = warp & 3, wn = warp >> 2;
    int gid = lane >> 2, tq = lane & 3;

    float acc[2][8][4];
    #pragma unroll
    for (int mt = 0; mt < 2; mt++)
        #pragma unroll
        for (int nt = 0; nt < 8; nt++)
            #pragma unroll
            for (int q = 0; q < 4; q++) acc[mt][nt][q] = 0.f;

    const __nv_bfloat16* Asel[3] = {AHI, AHI, ALO};
    const __nv_bfloat16* Bsel[3] = {BHI, BLO, BHI};

    #pragma unroll
    for (int t = 0; t < 3; t++) {
        const __nv_bfloat16* As = Asel[t];
        const __nv_bfloat16* Bs = Bsel[t];
        #pragma unroll
        for (int ks = 0; ks < 4; ks++) {
            int k0 = ks*16;
            uint32_t a[2][4], b[8][2];
            #pragma unroll
            for (int mt = 0; mt < 2; mt++) {
                const __nv_bfloat16* p = As + (wm*32 + mt*16 + gid)*EST + k0 + tq*2;
                a[mt][0] = *(const uint32_t*)(p);
                a[mt][1] = *(const uint32_t*)(p + 8*EST);
                a[mt][2] = *(const uint32_t*)(p + 8);
                a[mt][3] = *(const uint32_t*)(p + 8*EST + 8);
            }
            #pragma unroll
            for (int nt = 0; nt < 8; nt++) {
                const __nv_bfloat16* p = Bs + (wn*64 + nt*8 + gid)*EST + k0 + tq*2;
                b[nt][0] = *(const uint32_t*)(p);
                b[nt][1] = *(const uint32_t*)(p + 8);
            }
            #pragma unroll
            for (int mt = 0; mt < 2; mt++)
                #pragma unroll
                for (int nt = 0; nt < 8; nt++)
                    mma16816(acc[mt][nt], a[mt], b[nt]);
        }
    }

    #pragma unroll
    for (int mt = 0; mt < 2; mt++) {
        int r0 = e0 + wm*32 + mt*16 + gid;
        #pragma unroll
        for (int nt = 0; nt < 8; nt++) {
            int col = wn*64 + nt*8 + tq*2;
            float2 v0 = make_float2(acc[mt][nt][0], acc[mt][nt][1]);
            float2 v1 = make_float2(acc[mt][nt][2], acc[mt][nt][3]);
            *(float2*)(g_R + (size_t)r0*128 + col)     = v0;
            *(float2*)(g_R + (size_t)(r0+8)*128 + col) = v1;
        }
    }
}

// ============================================================================
// 5. Attention core: one warp per (node, head); K/V = R[edge] + P[nbr]
// ============================================================================
__global__ void attn_kernel(const float* __restrict__ maskp)
{
    __shared__ float Ks[8][KNB*DH];
    __shared__ float Vs[8][KNB*DH];
    __shared__ float att[8][32];
    __shared__ float qv[8][16];
    __shared__ int   snb[8][32];

    int tid = threadIdx.x;
    int ws = tid >> 5, lane = tid & 31;
    int w = blockIdx.x * 8 + ws;
    int node = w >> 2;
    int head = w & 3;

    if (lane < 16) qv[ws][lane] = g_Q[(size_t)node*64 + head*16 + lane];
    float ma = 0.f;
    if (lane < KNB) {
        int b = node / L_;
        int nbr = b*L_ + g_idx[node*KNB + lane];
        snb[ws][lane] = nbr;
        ma = maskp[nbr] * maskp[node];
    }
    __syncwarp();
    for (int idx = lane; idx < KNB*DH; idx += 32) {
        int k = idx >> 4, d = idx & 15;
        int nb = snb[ws][k];
        size_t br = (size_t)(node*KNB + k)*128 + head*16 + d;
        size_t bp = (size_t)nb*128 + head*16 + d;
        Ks[ws][idx] = g_R[br]      + g_P[bp];
        Vs[ws][idx] = g_R[br + 64] + g_P[bp + 64];
    }
    __syncwarp();

    const float NEGMIN = -3.402823466e38f;
    float lg = NEGMIN;
    if (lane < KNB) {
        float s = 0.f;
        #pragma unroll
        for (int d = 0; d < 16; d++) s += qv[ws][d] * Ks[ws][lane*16 + d];
        s *= 0.25f;
        lg = (ma > 0.f) ? s : NEGMIN;
    }
    float mx = lg;
    #pragma unroll
    for (int off = 16; off; off >>= 1)
        mx = fmaxf(mx, __shfl_xor_sync(0xffffffffu, mx, off));
    float p = (lane < KNB) ? expf(lg - mx) : 0.f;
    float sum = p;
    #pragma unroll
    for (int off = 16; off; off >>= 1)
        sum += __shfl_xor_sync(0xffffffffu, sum, off);
    float at = (lane < KNB) ? (p / sum) * ma : 0.f;
    att[ws][lane] = at;
    __syncwarp();

    if (lane < 16) {
        float u = 0.f;
        #pragma unroll
        for (int k = 0; k < KNB; k++) u += att[ws][k] * Vs[ws][k*16 + lane];
        g_upd[(size_t)node*64 + head*16 + lane] = u;
    }
}

// ============================================================================
// 6. GEMM (K x 64) + bias + residual + LayerNorm (+ optional mask) epilogue
// ============================================================================
__global__ void gemm_ln_kernel(const float* __restrict__ A,
                               const float* __restrict__ Bw,
                               const float* __restrict__ bias,
                               const float* __restrict__ resid,
                               const float* __restrict__ gamma,
                               const float* __restrict__ beta,
                               const float* __restrict__ maskp,
                               float* __restrict__ Out,
                               int K)
{
    __shared__ float As[16][128];
    __shared__ float Bs[16][64];
    __shared__ float Cs[128][65];
    int tid = threadIdx.x;
    int tx = tid & 15, ty = tid >> 4;
    int m0 = blockIdx.x * 128;

    float acc[8][4];
    #pragma unroll
    for (int i = 0; i < 8; i++)
        #pragma unroll
        for (int j = 0; j < 4; j++) acc[i][j] = 0.f;

    for (int k0 = 0; k0 < K; k0 += 16) {
        #pragma unroll
        for (int i = 0; i < 8; i++) {
            int idx = tid + i*256;
            int m = idx >> 4, kk = idx & 15;
            As[kk][m] = A[(size_t)(m0+m)*K + k0 + kk];
        }
        #pragma unroll
        for (int i = 0; i < 4; i++) {
            int idx = tid + i*256;
            int kk = idx >> 6, n = idx & 63;
            Bs[kk][n] = Bw[(size_t)(k0+kk)*64 + n];
        }
        __syncthreads();
        #pragma unroll
        for (int kk = 0; kk < 16; kk++) {
            float a[8], bb[4];
            #pragma unroll
            for (int i = 0; i < 8; i++) a[i] = As[kk][ty*8 + i];
            #pragma unroll
            for (int j = 0; j < 4; j++) bb[j] = Bs[kk][tx + j*16];
            #pragma unroll
            for (int i = 0; i < 8; i++)
                #pragma unroll
                for (int j = 0; j < 4; j++) acc[i][j] += a[i]*bb[j];
        }
        __syncthreads();
    }
    #pragma unroll
    for (int j = 0; j < 4; j++) {
        int n = tx + j*16;
        float bv = bias[n];
        #pragma unroll
        for (int i = 0; i < 8; i++) {
            int row = ty*8 + i;
            Cs[row][n] = acc[i][j] + bv + resid[(size_t)(m0+row)*64 + n];
        }
    }
    __syncthreads();

    int wid = tid >> 5, lane = tid & 31;
    for (int r = 0; r < 16; r++) {
        int row = wid*16 + r;
        float x0 = Cs[row][lane], x1 = Cs[row][lane+32];
        float s = x0 + x1;
        #pragma unroll
        for (int off = 16; off; off >>= 1)
            s += __shfl_xor_sync(0xffffffffu, s, off);
        float mean = s * (1.f/64.f);
        float d0 = x0 - mean, d1 = x1 - mean;
        float vs = d0*d0 + d1*d1;
        #pragma unroll
        for (int off = 16; off; off >>= 1)
            vs += __shfl_xor_sync(0xffffffffu, vs, off);
        float inv = 1.f / sqrtf(vs*(1.f/64.f) + 1e-5f);
        float mk = maskp ? maskp[m0 + row] : 1.f;
        size_t ob = (size_t)(m0+row)*64;
        Out[ob + lane]      = (d0*inv*gamma[lane]    + beta[lane])    * mk;
        Out[ob + lane + 32] = (d1*inv*gamma[lane+32] + beta[lane+32]) * mk;
    }
}

// ============================================================================
// 7. Output head
// ============================================================================
__global__ void out_kernel(const float* __restrict__ Wout,
                           const float* __restrict__ bout,
                           float* __restrict__ out)
{
    int tid = threadIdx.x;
    int ws = tid >> 5, lane = tid & 31;
    int n = blockIdx.x * 8 + ws;
    float v = g_hV[(size_t)n*64 + lane] * Wout[lane]
            + g_hV[(size_t)n*64 + 32 + lane] * Wout[32 + lane];
    #pragma unroll
    for (int off = 16; off; off >>= 1)
        v += __shfl_xor_sync(0xffffffffu, v, off);
    if (lane == 0) out[n] = v + bout[0];
}

// ============================================================================
extern "C" void kernel_launch(void* const* d_in, const int* in_sizes, int n_in,
                              void* d_out, int out_size)
{
    const float* coords = (const float*)d_in[0];
    const float* nodef  = (const float*)d_in[1];
    const float* maskp  = (const float*)d_in[2];
    const float* W_node = (const float*)d_in[3];
    const float* b_node = (const float*)d_in[4];
    const float* W_ee   = (const float*)d_in[5];
    const float* g_eln  = (const float*)d_in[6];
    const float* b_eln  = (const float*)d_in[7];
    const float* W_ep   = (const float*)d_in[8];
    const float* b_ep   = (const float*)d_in[9];
    const float* WQ = (const float*)d_in[10];
    const float* bQ = (const float*)d_in[11];
    const float* WK = (const float*)d_in[12];
    const float* bK = (const float*)d_in[13];
    const float* WV = (const float*)d_in[14];
    const float* bV = (const float*)d_in[15];
    const float* WO = (const float*)d_in[16];
    const float* bO = (const float*)d_in[17];
    const float* g1 = (const float*)d_in[18];
    const float* b1 = (const float*)d_in[19];
    const float* W1 = (const float*)d_in[20];
    const float* bf1= (const float*)d_in[21];
    const float* W2 = (const float*)d_in[22];
    const float* bf2= (const float*)d_in[23];
    const float* g2 = (const float*)d_in[24];
    const float* b2 = (const float*)d_in[25];
    const float* W_out = (const float*)d_in[26];
    const float* b_out = (const float*)d_in[27];
    float* outp = (float*)d_out;

    void *pv;
    cudaGetSymbolAddress(&pv, g_hV);   float* p_hV   = (float*)pv;
    cudaGetSymbolAddress(&pv, g_upd);  float* p_upd  = (float*)pv;
    cudaGetSymbolAddress(&pv, g_hmid); float* p_hmid = (float*)pv;
    cudaGetSymbolAddress(&pv, g_ffn);  float* p_ffn  = (float*)pv;

    cudaFuncSetAttribute(kv_mma_kernel,
                         cudaFuncAttributeMaxDynamicSharedMemorySize, KV_SMEM);
    cudaFuncSetAttribute(knn_kernel,
                         cudaFuncAttributeMaxDynamicSharedMemorySize, 65536);

    knn_kernel<<<128, 256, 65536>>>(coords, maskp);
    edge_kernel<<<NE/16, 256>>>(W_ee, g_eln, b_eln, W_ep, b_ep);

    gemm_bias_kernel<<<dim3(NN/128, 1), 256>>>(nodef, W_node, b_node, p_hV,
                                               FDIM, HID_, HID_, 0);

    for (int l = 0; l < NLAYERS; l++) {
        const float* WQl = WQ + (size_t)l*HID_*HID_;
        const float* WKl = WK + (size_t)l*2*HID_*HID_;
        const float* WVl = WV + (size_t)l*2*HID_*HID_;
        const float* WOl = WO + (size_t)l*HID_*HID_;
        const float* W1l = W1 + (size_t)l*HID_*FFN;
        const float* W2l = W2 + (size_t)l*FFN*HID_;

        // Q | K-node | V-node in one launch (node halves of WK/WV are rows 64..127)
        qp_kernel<<<dim3(NN/128, 3), 256>>>(p_hV, WQl, bQ + l*HID_,
                                            WKl + 64*64, bK + l*HID_,
                                            WVl + 64*64, bV + l*HID_);
        // edge-half weights -> bf16 hi/lo
        kv_prep_kernel<<<32, 256>>>(WKl, WVl);
        // edge term: R = h_E @ [WK[0:64] | WV[0:64]]  (bf16 3-term MMA)
        kv_mma_kernel<<<NE/128, 256, KV_SMEM>>>();
        // attention (K/V = R + P[nbr])
        attn_kernel<<<NN*NH/8, 256>>>(maskp);
        // h_mid = LN(h_V + upd@WO + bO)
        gemm_ln_kernel<<<NN/128, 256>>>(p_upd, WOl, bO + l*HID_, p_hV,
                                        g1 + l*HID_, b1 + l*HID_, nullptr,
                                        p_hmid, HID_);
        // ffn = relu(h_mid @ W1 + bf1)
        gemm_bias_kernel<<<dim3(NN/128, 4), 256>>>(p_hmid, W1l, bf1 + l*FFN, p_ffn,
                                                   HID_, FFN, FFN, 1);
        // h_V = LN(h_mid + ffn@W2 + bf2) * mask
        gemm_ln_kernel<<<NN/128, 256>>>(p_ffn, W2l, bf2 + l*HID_, p_hmid,
                                        g2 + l*HID_, b2 + l*HID_, maskp,
                                        p_hV, FFN);
    }

    out_kernel<<<NN/8, 256>>>(W_out, b_out, outp);
}